// round 12
// baseline (speedup 1.0000x reference)
#include <cuda_runtime.h>
#include <cuda_fp16.h>

#define SEQ   512
#define BATCH 64
#define HID   1024
#define EMB   1024
#define G3    (3*HID)        // 3072
#define RGRID 128            // recurrent CTAs
#define PGRID 20             // gi producer CTAs (co-resident; GB300 has 152 SMs)
#define RTHR  256            // 8 warps
#define NCELL 8              // barrier counter cells
#define NTILE 24             // gi tiles per t-pair (3072/128)

// ---------------- device scratch ----------------
__device__ __half d_Xh [SEQ*BATCH*EMB];        // 64 MB  gathered embeddings [m][k]
__device__ __half d_Wih[G3*EMB];               // 6 MB   W_ih fp16 [n][k]
__device__ __half d_gih[(size_t)SEQ*G3*BATCH]; // 201 MB gi fp16 [t][n][b]
__device__ __half d_hh [2][BATCH*HID];         // h fp16 double buffer [b][n]
__device__ unsigned int d_barc[NCELL*32];      // distributed barrier cells (128B apart)
__device__ unsigned int d_gflag[SEQ/2];        // per t-pair tile-completion counters

// ---------------- mma m16n8k16 f16 x f16 -> f32 ----------------
__device__ __forceinline__ void mma16816(float* d, const unsigned* a, const unsigned* b) {
    asm volatile(
        "mma.sync.aligned.m16n8k16.row.col.f32.f16.f16.f32 "
        "{%0,%1,%2,%3}, {%4,%5,%6,%7}, {%8,%9}, {%0,%1,%2,%3};\n"
        : "+f"(d[0]), "+f"(d[1]), "+f"(d[2]), "+f"(d[3])
        : "r"(a[0]), "r"(a[1]), "r"(a[2]), "r"(a[3]), "r"(b[0]), "r"(b[1]));
}

__device__ __forceinline__ unsigned smaddr(const void* p) {
    return (unsigned)__cvta_generic_to_shared(p);
}

// R5-verbatim cp.async macros (producer path only; PASSED)
#define CP_ASYNC16(dst, src) \
    asm volatile("cp.async.ca.shared.global [%0], [%1], 16;" :: "r"(dst), "l"(src))
#define CP_COMMIT()  asm volatile("cp.async.commit_group;")
#define CP_WAIT0()   asm volatile("cp.async.wait_group 0;")

// ---------------- prep ----------------
__global__ void k_convert_wih(const float* __restrict__ W) {
    int n = G3*EMB;
    for (int i = blockIdx.x*blockDim.x + threadIdx.x; i < n; i += gridDim.x*blockDim.x)
        d_Wih[i] = __float2half_rn(W[i]);
}

__global__ void k_gather(const int* __restrict__ idx, const float* __restrict__ emb) {
    size_t n = (size_t)SEQ*BATCH*EMB;
    for (size_t i = (size_t)blockIdx.x*blockDim.x + threadIdx.x; i < n; i += (size_t)gridDim.x*blockDim.x) {
        int k = (int)(i & (EMB-1));
        int m = (int)(i >> 10);
        d_Xh[i] = __float2half_rn(emb[(size_t)idx[m]*EMB + k]);
    }
}

__global__ void k_init_h(const float* __restrict__ h0) {
    int i = blockIdx.x*blockDim.x + threadIdx.x;
    if (i < NCELL*32) d_barc[i] = 0u;
    if (i < SEQ/2)    d_gflag[i] = 0u;
    if (i < BATCH*HID)
        d_hh[0][i] = __float2half_rn(h0[i]);
}

// ---------------- producer: one gi tile (EXACT R5 gi_gemm body) ----------------
// tile tau: m0 = (tau/NTILE)*128 (2 timesteps), n0 = (tau%NTILE)*128
__device__ void gi_tile(char* smem, const float* __restrict__ b_ih, int tau) {
    __half* As = (__half*)smem;             // 2 x 5120 halfs
    __half* Bs = As + 2*5120;               // 2 x 5120 halfs

    const int m0  = (tau / NTILE) * 128;
    const int n0  = (tau % NTILE) * 128;
    const int tid = threadIdx.x;
    const int lane = tid & 31, w = tid >> 5;
    const int wm = (w & 1) * 64;
    const int wn = (w >> 1) * 32;
    const int g  = lane >> 2, tg = lane & 3;

    const __half* Aglob = d_Wih + (size_t)n0 * EMB;
    const __half* Bglob = d_Xh  + (size_t)m0 * EMB;

    const int srow = tid >> 2, sq = tid & 3;
    const int srow2 = (tid + 256) >> 2, sq2 = (tid + 256) & 3;

    const int a_row = (lane & 7) + ((lane >> 3) & 1) * 8;
    const int a_c8  = (lane >> 4) * 8;
    const int b_row = (lane & 7) + ((lane >> 4) & 1) * 8;
    const int b_c8  = ((lane >> 3) & 1) * 8;

    float acc[4][4][4];
#pragma unroll
    for (int mi = 0; mi < 4; mi++)
#pragma unroll
        for (int nf = 0; nf < 4; nf++)
#pragma unroll
            for (int q = 0; q < 4; q++) acc[mi][nf][q] = 0.f;

    CP_ASYNC16(smaddr(&As[srow*40  + sq*8]),         &Aglob[(size_t)srow*EMB  + sq*8]);
    CP_ASYNC16(smaddr(&As[srow2*40 + sq2*8]),        &Aglob[(size_t)srow2*EMB + sq2*8]);
    CP_ASYNC16(smaddr(&Bs[srow*40  + sq*8]),         &Bglob[(size_t)srow*EMB  + sq*8]);
    CP_ASYNC16(smaddr(&Bs[srow2*40 + sq2*8]),        &Bglob[(size_t)srow2*EMB + sq2*8]);
    CP_COMMIT();
    CP_WAIT0();
    __syncthreads();

    int buf = 0;
    for (int k0 = 0; k0 < EMB; k0 += 32) {
        const bool more = (k0 + 32 < EMB);
        if (more) {
            int kn = k0 + 32;
            int bo = (buf^1)*5120;
            CP_ASYNC16(smaddr(&As[bo + srow*40  + sq*8]),  &Aglob[(size_t)srow*EMB  + kn + sq*8]);
            CP_ASYNC16(smaddr(&As[bo + srow2*40 + sq2*8]), &Aglob[(size_t)srow2*EMB + kn + sq2*8]);
            CP_ASYNC16(smaddr(&Bs[bo + srow*40  + sq*8]),  &Bglob[(size_t)srow*EMB  + kn + sq*8]);
            CP_ASYNC16(smaddr(&Bs[bo + srow2*40 + sq2*8]), &Bglob[(size_t)srow2*EMB + kn + sq2*8]);
            CP_COMMIT();
        }
        const unsigned abase = smaddr(&As[buf*5120]);
        const unsigned bbase = smaddr(&Bs[buf*5120]);
#pragma unroll
        for (int kk = 0; kk < 32; kk += 16) {
            unsigned a[4][4], b[4][2];
#pragma unroll
            for (int mi = 0; mi < 4; mi++) {
                unsigned addr = abase + (unsigned)(((wm + mi*16 + a_row)*40 + kk + a_c8) * 2);
                asm volatile("ldmatrix.sync.aligned.m8n8.x4.shared.b16 {%0,%1,%2,%3}, [%4];"
                             : "=r"(a[mi][0]), "=r"(a[mi][1]), "=r"(a[mi][2]), "=r"(a[mi][3])
                             : "r"(addr));
            }
#pragma unroll
            for (int nf2 = 0; nf2 < 2; nf2++) {
                unsigned r0, r1, r2, r3;
                unsigned addr = bbase + (unsigned)(((wn + nf2*16 + b_row)*40 + kk + b_c8) * 2);
                asm volatile("ldmatrix.sync.aligned.m8n8.x4.shared.b16 {%0,%1,%2,%3}, [%4];"
                             : "=r"(r0), "=r"(r1), "=r"(r2), "=r"(r3) : "r"(addr));
                b[nf2*2][0] = r0; b[nf2*2][1] = r1;
                b[nf2*2+1][0] = r2; b[nf2*2+1][1] = r3;
            }
#pragma unroll
            for (int mi = 0; mi < 4; mi++)
#pragma unroll
                for (int nf = 0; nf < 4; nf++)
                    mma16816(acc[mi][nf], a[mi], b[nf]);
        }
        if (more) {
            CP_WAIT0();
            __syncthreads();
            buf ^= 1;
        }
    }

    const int mcol = wn + 2*tg;
    const int t    = (m0 >> 6) + (wn >> 6);
#pragma unroll
    for (int mi = 0; mi < 4; mi++) {
        int nrow0 = n0 + wm + mi*16 + g;
        float bias0 = __ldg(&b_ih[nrow0]);
        float bias8 = __ldg(&b_ih[nrow0 + 8]);
#pragma unroll
        for (int nf = 0; nf < 4; nf++) {
            int b = (mcol + nf*8) & 63;
            __half2 v01 = __floats2half2_rn(acc[mi][nf][0] + bias0, acc[mi][nf][1] + bias0);
            __half2 v23 = __floats2half2_rn(acc[mi][nf][2] + bias8, acc[mi][nf][3] + bias8);
            size_t o0 = ((size_t)t*G3 + nrow0)*64 + b;
            *(__half2*)&d_gih[o0]        = v01;
            *(__half2*)&d_gih[o0 + 8*64] = v23;
        }
    }

    // publish: all stores visible, then bump the t-pair flag
    __threadfence();
    __syncthreads();
    if (threadIdx.x == 0) atomicAdd(&d_gflag[tau / NTILE], 1u);
}

// load/store one 16-row chunk of the warp's h slice through registers (plain ops)
#define LD_CHUNK(v, ch) do {                                                    \
    _Pragma("unroll")                                                           \
    for (int i2 = 0; i2 < 8; i2++) {                                            \
        int idx_ = (ch)*256 + i2*32 + lane;                                     \
        int row_ = idx_ >> 4, q_ = idx_ & 15;                                   \
        (v)[i2] = __ldcg((const uint4*)&hrd[row_*HID + kw + q_*8]);             \
    }                                                                           \
} while (0)

#define ST_CHUNK(v, ch) do {                                                    \
    _Pragma("unroll")                                                           \
    for (int i2 = 0; i2 < 8; i2++) {                                            \
        int idx_ = (ch)*256 + i2*32 + lane;                                     \
        int row_ = idx_ >> 4, q_ = idx_ & 15;                                   \
        *(uint4*)&hsw[row_*136 + q_*8] = (v)[i2];                               \
    }                                                                           \
} while (0)

#define MMA_MT(mt) do {                                                         \
    _Pragma("unroll")                                                           \
    for (int s = 0; s < 8; s++) {                                               \
        unsigned a_[4];                                                         \
        unsigned addr_ = lm_base + (unsigned)((mt)*4352 + s*32);                \
        asm volatile("ldmatrix.sync.aligned.m8n8.x4.shared.b16 {%0,%1,%2,%3}, [%4];" \
                     : "=r"(a_[0]), "=r"(a_[1]), "=r"(a_[2]), "=r"(a_[3]) : "r"(addr_)); \
        _Pragma("unroll")                                                       \
        for (int j = 0; j < 3; j++)                                             \
            mma16816(acc[(mt)][j], a_, Whh[s][j]);                              \
    }                                                                           \
} while (0)

// ---------------- fused persistent kernel ----------------
// blockIdx.x < RGRID: recurrent consumer (R10-proven body).
// blockIdx.x >= RGRID: gi producer, tiles tau = pid, pid+PGRID, ... (t-major).
// Consumer spins on d_gflag[(t+1)>>1] >= NTILE inside the barrier-wait window.
__global__ __launch_bounds__(RTHR, 1) void k_fused(const float* __restrict__ hidden,
                                                   const float* __restrict__ W_hh,
                                                   const float* __restrict__ b_hh,
                                                   const float* __restrict__ b_ih,
                                                   float* __restrict__ out) {
    extern __shared__ char smem[];

    if (blockIdx.x >= RGRID) {
        // ---------- producer ----------
        int pid = blockIdx.x - RGRID;
        for (int tau = pid; tau < (SEQ/2)*NTILE; tau += PGRID)
            gi_tile(smem, b_ih, tau);
        return;
    }

    // ---------- recurrent consumer (R10 body) ----------
    const int c    = blockIdx.x;
    const int hid0 = c * 8;
    const int tid  = threadIdx.x;
    const int lane = tid & 31, w = tid >> 5;
    const int g = lane >> 2, tg = lane & 3;
    const int kw = w * 128;

    __half* hsw = (__half*)(smem + w*17408);
    float*  h32 = (float*)(smem + 139264);

    for (int i = tid; i < 512; i += RTHR) {
        int gg = i >> 6, b = i & 63;
        h32[i] = hidden[b*HID + hid0 + gg];
    }

    // W_hh fragments (registers, once)
    unsigned Whh[8][3][2];
#pragma unroll
    for (int s = 0; s < 8; s++) {
#pragma unroll
        for (int j = 0; j < 3; j++) {
            int row = j*1024 + hid0 + g;
            int k0  = kw + s*16 + 2*tg;
            float2 v0 = *(const float2*)&W_hh[(size_t)row*HID + k0];
            float2 v1 = *(const float2*)&W_hh[(size_t)row*HID + k0 + 8];
            __half2 a0 = __floats2half2_rn(v0.x, v0.y);
            __half2 a1 = __floats2half2_rn(v1.x, v1.y);
            Whh[s][j][0] = *(unsigned*)&a0;
            Whh[s][j][1] = *(unsigned*)&a1;
        }
    }

    const int b_o  = tid >> 2;
    const int gg_o = (2*tid) & 7;
    const float br0 = b_hh[hid0 + gg_o],        br1 = b_hh[hid0 + gg_o + 1];
    const float bz0 = b_hh[1024 + hid0 + gg_o], bz1 = b_hh[1024 + hid0 + gg_o + 1];
    const float bn0 = b_hh[2048 + hid0 + gg_o], bn1 = b_hh[2048 + hid0 + gg_o + 1];

    const int r8 = lane & 7, quad = lane >> 3;
    const unsigned lm_base = smaddr(hsw) + (unsigned)(((r8 + (quad & 1)*8)*136 + (quad >> 1)*8) * 2);

    // wait for gi[0] (t-pair 0) before entering the loop
    if (tid == 0) {
        unsigned v;
        do {
            asm volatile("ld.global.cg.u32 %0, [%1];" : "=r"(v) : "l"(&d_gflag[0]));
            if (v >= NTILE) break;
            __nanosleep(64);
        } while (true);
    }
    __syncthreads();

    for (int t = 0; t < SEQ; ++t) {
        const __half* hrd = d_hh[t & 1];          // read buffer
        __half*       hwr = d_hh[(t + 1) & 1];    // write buffer

        // ---- prefetch gi[t] (flag verified last iteration / pre-loop) ----
        float gir0, gir1, giz0, giz1, gin0, gin1;
        {
            const __half* gp = d_gih + (size_t)t * G3 * 64;
            gir0 = __half2float(gp[(hid0+gg_o)*64 + b_o]);
            gir1 = __half2float(gp[(hid0+gg_o+1)*64 + b_o]);
            giz0 = __half2float(gp[(1024+hid0+gg_o)*64 + b_o]);
            giz1 = __half2float(gp[(1024+hid0+gg_o+1)*64 + b_o]);
            gin0 = __half2float(gp[(2048+hid0+gg_o)*64 + b_o]);
            gin1 = __half2float(gp[(2048+hid0+gg_o+1)*64 + b_o]);
        }

        float acc[4][3][4];
#pragma unroll
        for (int mt = 0; mt < 4; mt++)
#pragma unroll
            for (int j = 0; j < 3; j++)
#pragma unroll
                for (int q = 0; q < 4; q++) acc[mt][j][q] = 0.f;

        // ---- register-pipelined h load + MMA (R10-proven) ----
        uint4 v0[8], v1[8];
        LD_CHUNK(v0, 0);
        LD_CHUNK(v1, 1);
        ST_CHUNK(v0, 0); __syncwarp();
        LD_CHUNK(v0, 2);
        MMA_MT(0);
        ST_CHUNK(v1, 1); __syncwarp();
        LD_CHUNK(v1, 3);
        MMA_MT(1);
        ST_CHUNK(v0, 2); __syncwarp();
        MMA_MT(2);
        ST_CHUNK(v1, 3); __syncwarp();
        MMA_MT(3);

        // ---- write split-K partials (overlay own h slice; all reads done) ----
        float* redw = (float*)(smem + w*17408);
#pragma unroll
        for (int mt = 0; mt < 4; mt++)
#pragma unroll
            for (int j = 0; j < 3; j++) {
                int col = j*8 + 2*tg;
                *(float2*)&redw[(mt*16 + g)*24 + col]     = make_float2(acc[mt][j][0], acc[mt][j][1]);
                *(float2*)&redw[(mt*16 + g + 8)*24 + col] = make_float2(acc[mt][j][2], acc[mt][j][3]);
            }
        __syncthreads();

        // ---- reduce + gates ----
        float s0r=0,s1r=0,s0z=0,s1z=0,s0n=0,s1n=0;
#pragma unroll
        for (int ww = 0; ww < 8; ww++) {
            const float* rw = (const float*)(smem + ww*17408);
            float2 rr = *(const float2*)&rw[b_o*24 + gg_o];
            float2 zz = *(const float2*)&rw[b_o*24 + 8 + gg_o];
            float2 nn = *(const float2*)&rw[b_o*24 + 16 + gg_o];
            s0r += rr.x; s1r += rr.y; s0z += zz.x; s1z += zz.y; s0n += nn.x; s1n += nn.y;
        }
        float r0 = 1.f / (1.f + __expf(-(gir0 + s0r + br0)));
        float r1 = 1.f / (1.f + __expf(-(gir1 + s1r + br1)));
        float z0 = 1.f / (1.f + __expf(-(giz0 + s0z + bz0)));
        float z1 = 1.f / (1.f + __expf(-(giz1 + s1z + bz1)));
        float n0 = tanhf(gin0 + r0 * (s0n + bn0));
        float n1 = tanhf(gin1 + r1 * (s1n + bn1));
        float h0 = h32[gg_o*64 + b_o];
        float h1 = h32[(gg_o+1)*64 + b_o];
        float hn0 = (1.f - z0) * n0 + z0 * h0;
        float hn1 = (1.f - z1) * n1 + z1 * h1;
        h32[gg_o*64 + b_o]     = hn0;
        h32[(gg_o+1)*64 + b_o] = hn1;

        // h store (to the OTHER buffer) must be globally visible before arrive
        __half2 hv = __floats2half2_rn(hn0, hn1);
        *(__half2*)&hwr[b_o*HID + hid0 + gg_o] = hv;
        __threadfence();
        __syncthreads();

        // ---- early arrive on distributed cell ----
        if (tid == 0) atomicAdd(&d_barc[(c & 7) * 32], 1u);

        // overlap with barrier skew: output store
        *(float2*)&out[((size_t)t*64 + b_o)*HID + hid0 + gg_o] = make_float2(hn0, hn1);

        // ---- wait: threads 0..7 spin cells; thread 8 spins gi flag for t+1 ----
        if (tid < NCELL) {
            unsigned goal = (unsigned)(t + 1) * (RGRID / NCELL);
            unsigned v;
            const unsigned* cp = &d_barc[tid * 32];
            do {
                asm volatile("ld.global.cg.u32 %0, [%1];" : "=r"(v) : "l"(cp));
                if (v >= goal) break;
                __nanosleep(8);
            } while (true);
            __threadfence();
        } else if (tid == NCELL && (t + 1) < SEQ) {
            unsigned v;
            const unsigned* fp = &d_gflag[(t + 1) >> 1];
            do {
                asm volatile("ld.global.cg.u32 %0, [%1];" : "=r"(v) : "l"(fp));
                if (v >= NTILE) break;
                __nanosleep(8);
            } while (true);
        }
        __syncthreads();
    }
}

// ---------------- launch ----------------
extern "C" void kernel_launch(void* const* d_in, const int* in_sizes, int n_in,
                              void* d_out, int out_size) {
    (void)in_sizes; (void)n_in; (void)out_size;
    const int*   input  = (const int*)  d_in[0];
    const float* hidden = (const float*)d_in[2];
    const float* emb    = (const float*)d_in[3];
    const float* W_ih   = (const float*)d_in[4];
    const float* W_hh   = (const float*)d_in[5];
    const float* b_ih   = (const float*)d_in[6];
    const float* b_hh   = (const float*)d_in[7];
    float* out = (float*)d_out;

    const int RSMEM = 139264 + 2048;   // recurrent layout (producer uses first 41KB)
    cudaFuncSetAttribute(k_fused, cudaFuncAttributeMaxDynamicSharedMemorySize, RSMEM);

    k_convert_wih<<<3072, 256>>>(W_ih);
    k_gather<<<8192, 256>>>(input, emb);
    k_init_h<<<256, 256>>>(hidden);

    k_fused<<<RGRID + PGRID, RTHR, RSMEM>>>(hidden, W_hh, b_hh, b_ih, out);
}

// round 14
// speedup vs baseline: 2.1606x; 2.1606x over previous
#include <cuda_runtime.h>
#include <cuda_fp16.h>

#define SEQ   512
#define BATCH 64
#define HID   1024
#define EMB   1024
#define G3    (3*HID)        // 3072
#define RGRID 128
#define RTHR  256            // 8 warps
#define NCELL 8              // barrier counter cells

// ---------------- device scratch ----------------
__device__ __half d_Xh [SEQ*BATCH*EMB];        // 64 MB  gathered embeddings [m][k]
__device__ __half d_Wih[G3*EMB];               // 6 MB   W_ih fp16 [n][k]
__device__ __half d_gih[(size_t)SEQ*G3*BATCH]; // 201 MB gi fp16 [t][n][b]
__device__ __half d_hh [2][BATCH*HID];         // h fp16 double buffer [b][n]
__device__ unsigned int d_barc[NCELL*32];      // distributed barrier cells (128B apart)

// ---------------- mma m16n8k16 f16 x f16 -> f32 ----------------
__device__ __forceinline__ void mma16816(float* d, const unsigned* a, const unsigned* b) {
    asm volatile(
        "mma.sync.aligned.m16n8k16.row.col.f32.f16.f16.f32 "
        "{%0,%1,%2,%3}, {%4,%5,%6,%7}, {%8,%9}, {%0,%1,%2,%3};\n"
        : "+f"(d[0]), "+f"(d[1]), "+f"(d[2]), "+f"(d[3])
        : "r"(a[0]), "r"(a[1]), "r"(a[2]), "r"(a[3]), "r"(b[0]), "r"(b[1]));
}

__device__ __forceinline__ unsigned smaddr(const void* p) {
    return (unsigned)__cvta_generic_to_shared(p);
}

// R5-verbatim cp.async macros (gi GEMM only; PASSED)
#define CP_ASYNC16(dst, src) \
    asm volatile("cp.async.ca.shared.global [%0], [%1], 16;" :: "r"(dst), "l"(src))
#define CP_COMMIT()  asm volatile("cp.async.commit_group;")
#define CP_WAIT0()   asm volatile("cp.async.wait_group 0;")

// ---------------- prep ----------------
__global__ void k_convert_wih(const float* __restrict__ W) {
    int n = G3*EMB;
    for (int i = blockIdx.x*blockDim.x + threadIdx.x; i < n; i += gridDim.x*blockDim.x)
        d_Wih[i] = __float2half_rn(W[i]);
}

__global__ void k_gather(const int* __restrict__ idx, const float* __restrict__ emb) {
    size_t n = (size_t)SEQ*BATCH*EMB;
    for (size_t i = (size_t)blockIdx.x*blockDim.x + threadIdx.x; i < n; i += (size_t)gridDim.x*blockDim.x) {
        int k = (int)(i & (EMB-1));
        int m = (int)(i >> 10);
        d_Xh[i] = __float2half_rn(emb[(size_t)idx[m]*EMB + k]);
    }
}

__global__ void k_init_h(const float* __restrict__ h0) {
    int i = blockIdx.x*blockDim.x + threadIdx.x;
    if (i < NCELL*32) d_barc[i] = 0u;
    if (i < BATCH*HID)
        d_hh[0][i] = __float2half_rn(h0[i]);
}

// ---------------- gi GEMM v4b: 4 warps, warp tile 64x64, 2 CTAs/SM ----------------
// gi[t][n][b] = sum_k W_ih[n][k]*X[m][k] + b_ih[n],  m = t*64+b
// CTA tile: 128(n) x 128(m = 2 timesteps), K step 32, cp.async double buffer.
// R13 bug fixed: B uses the R5-proven B lane pattern (k-halves in consecutive
// regs), NOT the A pattern.
__global__ __launch_bounds__(128, 2) void k_gi_gemm(const float* __restrict__ b_ih) {
    __shared__ __half As[2][128*40];
    __shared__ __half Bs[2][128*40];

    const int m0  = blockIdx.y * 128;
    const int n0  = blockIdx.x * 128;
    const int tid = threadIdx.x;
    const int lane = tid & 31, w = tid >> 5;   // 4 warps
    const int wm = (w & 1) * 64;    // n offset within 128
    const int wn = (w >> 1) * 64;   // m offset within 128
    const int g  = lane >> 2, tg = lane & 3;

    const __half* Aglob = d_Wih + (size_t)n0 * EMB;
    const __half* Bglob = d_Xh  + (size_t)m0 * EMB;

    // A lane pattern: (r0,r1,r2,r3) = (m0k0, m8k0, m0k8, m8k8)
    const int a_row = (lane & 7) + ((lane >> 3) & 1) * 8;
    const int a_c8  = (lane >> 4) * 8;
    // B lane pattern (R5-proven): (r0,r1,r2,r3) = (n0k0, n0k8, n8k0, n8k8)
    const int b_row = (lane & 7) + ((lane >> 4) & 1) * 8;
    const int b_c8  = ((lane >> 3) & 1) * 8;

    float acc[4][8][4];
#pragma unroll
    for (int mi = 0; mi < 4; mi++)
#pragma unroll
        for (int nf = 0; nf < 8; nf++)
#pragma unroll
            for (int q = 0; q < 4; q++) acc[mi][nf][q] = 0.f;

    // prologue: stage k0=0 into buf 0 (4 chunks per thread per matrix)
#pragma unroll
    for (int j = 0; j < 4; j++) {
        int u = tid + j*128, row = u >> 2, q = u & 3;
        CP_ASYNC16(smaddr(&As[0][row*40 + q*8]), &Aglob[(size_t)row*EMB + q*8]);
        CP_ASYNC16(smaddr(&Bs[0][row*40 + q*8]), &Bglob[(size_t)row*EMB + q*8]);
    }
    CP_COMMIT();
    CP_WAIT0();
    __syncthreads();

    int buf = 0;
    for (int k0 = 0; k0 < EMB; k0 += 32) {
        const bool more = (k0 + 32 < EMB);
        if (more) {
            int kn = k0 + 32;
#pragma unroll
            for (int j = 0; j < 4; j++) {
                int u = tid + j*128, row = u >> 2, q = u & 3;
                CP_ASYNC16(smaddr(&As[buf^1][row*40 + q*8]), &Aglob[(size_t)row*EMB + kn + q*8]);
                CP_ASYNC16(smaddr(&Bs[buf^1][row*40 + q*8]), &Bglob[(size_t)row*EMB + kn + q*8]);
            }
            CP_COMMIT();
        }
        const unsigned abase = smaddr(&As[buf][0]);
        const unsigned bbase = smaddr(&Bs[buf][0]);
#pragma unroll
        for (int kk = 0; kk < 32; kk += 16) {
            unsigned a[4][4], b[8][2];
#pragma unroll
            for (int mi = 0; mi < 4; mi++) {
                unsigned addr = abase + (unsigned)(((wm + mi*16 + a_row)*40 + kk + a_c8) * 2);
                asm volatile("ldmatrix.sync.aligned.m8n8.x4.shared.b16 {%0,%1,%2,%3}, [%4];"
                             : "=r"(a[mi][0]), "=r"(a[mi][1]), "=r"(a[mi][2]), "=r"(a[mi][3])
                             : "r"(addr));
            }
#pragma unroll
            for (int nf2 = 0; nf2 < 4; nf2++) {
                unsigned r0, r1, r2, r3;
                unsigned addr = bbase + (unsigned)(((wn + nf2*16 + b_row)*40 + kk + b_c8) * 2);
                asm volatile("ldmatrix.sync.aligned.m8n8.x4.shared.b16 {%0,%1,%2,%3}, [%4];"
                             : "=r"(r0), "=r"(r1), "=r"(r2), "=r"(r3) : "r"(addr));
                // R5-proven pairing: {r0,r1} = n rows [0,8) k16 ; {r2,r3} = n rows [8,16)
                b[nf2*2][0] = r0; b[nf2*2][1] = r1;
                b[nf2*2+1][0] = r2; b[nf2*2+1][1] = r3;
            }
#pragma unroll
            for (int mi = 0; mi < 4; mi++)
#pragma unroll
                for (int nf = 0; nf < 8; nf++)
                    mma16816(acc[mi][nf], a[mi], b[nf]);
        }
        if (more) {
            CP_WAIT0();
            __syncthreads();
            buf ^= 1;
        }
    }

    // epilogue: gi fp16 [t][n][b] + b_ih.  wn multiple of 64 -> one t per warp
    const int t = (m0 >> 6) + (wn >> 6);
#pragma unroll
    for (int mi = 0; mi < 4; mi++) {
        int nrow0 = n0 + wm + mi*16 + g;
        float bias0 = __ldg(&b_ih[nrow0]);
        float bias8 = __ldg(&b_ih[nrow0 + 8]);
#pragma unroll
        for (int nf = 0; nf < 8; nf++) {
            int b = nf*8 + 2*tg;
            __half2 v01 = __floats2half2_rn(acc[mi][nf][0] + bias0, acc[mi][nf][1] + bias0);
            __half2 v23 = __floats2half2_rn(acc[mi][nf][2] + bias8, acc[mi][nf][3] + bias8);
            size_t o0 = ((size_t)t*G3 + nrow0)*64 + b;
            *(__half2*)&d_gih[o0]        = v01;
            *(__half2*)&d_gih[o0 + 8*64] = v23;
        }
    }
}

// load/store one 16-row chunk of the warp's h slice through registers (plain ops)
#define LD_CHUNK(v, ch) do {                                                    \
    _Pragma("unroll")                                                           \
    for (int i2 = 0; i2 < 8; i2++) {                                            \
        int idx_ = (ch)*256 + i2*32 + lane;                                     \
        int row_ = idx_ >> 4, q_ = idx_ & 15;                                   \
        (v)[i2] = __ldcg((const uint4*)&hrd[row_*HID + kw + q_*8]);             \
    }                                                                           \
} while (0)

#define ST_CHUNK(v, ch) do {                                                    \
    _Pragma("unroll")                                                           \
    for (int i2 = 0; i2 < 8; i2++) {                                            \
        int idx_ = (ch)*256 + i2*32 + lane;                                     \
        int row_ = idx_ >> 4, q_ = idx_ & 15;                                   \
        *(uint4*)&hsw[row_*136 + q_*8] = (v)[i2];                               \
    }                                                                           \
} while (0)

#define MMA_MT(mt) do {                                                         \
    _Pragma("unroll")                                                           \
    for (int s = 0; s < 8; s++) {                                               \
        unsigned a_[4];                                                         \
        unsigned addr_ = lm_base + (unsigned)((mt)*4352 + s*32);                \
        asm volatile("ldmatrix.sync.aligned.m8n8.x4.shared.b16 {%0,%1,%2,%3}, [%4];" \
                     : "=r"(a_[0]), "=r"(a_[1]), "=r"(a_[2]), "=r"(a_[3]) : "r"(addr_)); \
        _Pragma("unroll")                                                       \
        for (int j = 0; j < 3; j++)                                             \
            mma16816(acc[(mt)][j], a_, Whh[s][j]);                              \
    }                                                                           \
} while (0)

// ---------------- persistent recurrent kernel (EXACT R11 body — passed 3403us) --
__global__ __launch_bounds__(RTHR, 1) void k_recurrent(const float* __restrict__ hidden,
                                                       const float* __restrict__ W_hh,
                                                       const float* __restrict__ b_hh,
                                                       float* __restrict__ out) {
    extern __shared__ char smem[];
    const int c    = blockIdx.x;
    const int hid0 = c * 8;
    const int tid  = threadIdx.x;
    const int lane = tid & 31, w = tid >> 5;
    const int g = lane >> 2, tg = lane & 3;
    const int kw = w * 128;

    __half* hsw = (__half*)(smem + w*17408);
    float*  h32 = (float*)(smem + 139264);

    for (int i = tid; i < 512; i += RTHR) {
        int gg = i >> 6, b = i & 63;
        h32[i] = hidden[b*HID + hid0 + gg];
    }

    // W_hh fragments (registers, once)
    unsigned Whh[8][3][2];
#pragma unroll
    for (int s = 0; s < 8; s++) {
#pragma unroll
        for (int j = 0; j < 3; j++) {
            int row = j*1024 + hid0 + g;
            int k0  = kw + s*16 + 2*tg;
            float2 v0 = *(const float2*)&W_hh[(size_t)row*HID + k0];
            float2 v1 = *(const float2*)&W_hh[(size_t)row*HID + k0 + 8];
            __half2 a0 = __floats2half2_rn(v0.x, v0.y);
            __half2 a1 = __floats2half2_rn(v1.x, v1.y);
            Whh[s][j][0] = *(unsigned*)&a0;
            Whh[s][j][1] = *(unsigned*)&a1;
        }
    }

    const int b_o  = tid >> 2;
    const int gg_o = (2*tid) & 7;
    const float br0 = b_hh[hid0 + gg_o],        br1 = b_hh[hid0 + gg_o + 1];
    const float bz0 = b_hh[1024 + hid0 + gg_o], bz1 = b_hh[1024 + hid0 + gg_o + 1];
    const float bn0 = b_hh[2048 + hid0 + gg_o], bn1 = b_hh[2048 + hid0 + gg_o + 1];

    const int r8 = lane & 7, quad = lane >> 3;
    const unsigned lm_base = smaddr(hsw) + (unsigned)(((r8 + (quad & 1)*8)*136 + (quad >> 1)*8) * 2);

    // prefetch gi[0]
    float gir0, gir1, giz0, giz1, gin0, gin1;
    {
        const __half* gp = d_gih;
        gir0 = __half2float(gp[(hid0+gg_o)*64 + b_o]);
        gir1 = __half2float(gp[(hid0+gg_o+1)*64 + b_o]);
        giz0 = __half2float(gp[(1024+hid0+gg_o)*64 + b_o]);
        giz1 = __half2float(gp[(1024+hid0+gg_o+1)*64 + b_o]);
        gin0 = __half2float(gp[(2048+hid0+gg_o)*64 + b_o]);
        gin1 = __half2float(gp[(2048+hid0+gg_o+1)*64 + b_o]);
    }

    __syncthreads();

    for (int t = 0; t < SEQ; ++t) {
        const __half* hrd = d_hh[t & 1];          // read buffer
        __half*       hwr = d_hh[(t + 1) & 1];    // write buffer

        float acc[4][3][4];
#pragma unroll
        for (int mt = 0; mt < 4; mt++)
#pragma unroll
            for (int j = 0; j < 3; j++)
#pragma unroll
                for (int q = 0; q < 4; q++) acc[mt][j][q] = 0.f;

        // ---- register-pipelined h load + MMA (plain LDG/STS, R5 semantics) ----
        uint4 v0[8], v1[8];
        LD_CHUNK(v0, 0);
        LD_CHUNK(v1, 1);
        ST_CHUNK(v0, 0); __syncwarp();
        LD_CHUNK(v0, 2);
        MMA_MT(0);
        ST_CHUNK(v1, 1); __syncwarp();
        LD_CHUNK(v1, 3);
        MMA_MT(1);
        ST_CHUNK(v0, 2); __syncwarp();
        MMA_MT(2);
        ST_CHUNK(v1, 3); __syncwarp();
        MMA_MT(3);

        // ---- write split-K partials (overlay own h slice; all reads done) ----
        float* redw = (float*)(smem + w*17408);
#pragma unroll
        for (int mt = 0; mt < 4; mt++)
#pragma unroll
            for (int j = 0; j < 3; j++) {
                int col = j*8 + 2*tg;
                *(float2*)&redw[(mt*16 + g)*24 + col]     = make_float2(acc[mt][j][0], acc[mt][j][1]);
                *(float2*)&redw[(mt*16 + g + 8)*24 + col] = make_float2(acc[mt][j][2], acc[mt][j][3]);
            }
        __syncthreads();

        // ---- reduce + gates ----
        float s0r=0,s1r=0,s0z=0,s1z=0,s0n=0,s1n=0;
#pragma unroll
        for (int ww = 0; ww < 8; ww++) {
            const float* rw = (const float*)(smem + ww*17408);
            float2 rr = *(const float2*)&rw[b_o*24 + gg_o];
            float2 zz = *(const float2*)&rw[b_o*24 + 8 + gg_o];
            float2 nn = *(const float2*)&rw[b_o*24 + 16 + gg_o];
            s0r += rr.x; s1r += rr.y; s0z += zz.x; s1z += zz.y; s0n += nn.x; s1n += nn.y;
        }
        float r0 = 1.f / (1.f + __expf(-(gir0 + s0r + br0)));
        float r1 = 1.f / (1.f + __expf(-(gir1 + s1r + br1)));
        float z0 = 1.f / (1.f + __expf(-(giz0 + s0z + bz0)));
        float z1 = 1.f / (1.f + __expf(-(giz1 + s1z + bz1)));
        float n0 = tanhf(gin0 + r0 * (s0n + bn0));
        float n1 = tanhf(gin1 + r1 * (s1n + bn1));
        float h0 = h32[gg_o*64 + b_o];
        float h1 = h32[(gg_o+1)*64 + b_o];
        float hn0 = (1.f - z0) * n0 + z0 * h0;
        float hn1 = (1.f - z1) * n1 + z1 * h1;
        h32[gg_o*64 + b_o]     = hn0;
        h32[(gg_o+1)*64 + b_o] = hn1;

        // h store (to the OTHER buffer) must be globally visible before arrive
        __half2 hv = __floats2half2_rn(hn0, hn1);
        *(__half2*)&hwr[b_o*HID + hid0 + gg_o] = hv;
        __threadfence();
        __syncthreads();

        // ---- early arrive on distributed cell ----
        if (tid == 0) atomicAdd(&d_barc[(c & 7) * 32], 1u);

        // overlap with barrier skew: output store + next gi prefetch
        *(float2*)&out[((size_t)t*64 + b_o)*HID + hid0 + gg_o] = make_float2(hn0, hn1);
        if (t + 1 < SEQ) {
            const __half* gp = d_gih + (size_t)(t+1) * G3 * 64;
            gir0 = __half2float(gp[(hid0+gg_o)*64 + b_o]);
            gir1 = __half2float(gp[(hid0+gg_o+1)*64 + b_o]);
            giz0 = __half2float(gp[(1024+hid0+gg_o)*64 + b_o]);
            giz1 = __half2float(gp[(1024+hid0+gg_o+1)*64 + b_o]);
            gin0 = __half2float(gp[(2048+hid0+gg_o)*64 + b_o]);
            gin1 = __half2float(gp[(2048+hid0+gg_o+1)*64 + b_o]);
        }

        // ---- wait: thread i (0..7) spins on cell i ----
        if (tid < NCELL) {
            unsigned goal = (unsigned)(t + 1) * (RGRID / NCELL);
            unsigned v;
            const unsigned* cp = &d_barc[tid * 32];
            do {
                asm volatile("ld.global.cg.u32 %0, [%1];" : "=r"(v) : "l"(cp));
                if (v >= goal) break;
                __nanosleep(8);
            } while (true);
            __threadfence();
        }
        __syncthreads();
    }
}

// ---------------- launch ----------------
extern "C" void kernel_launch(void* const* d_in, const int* in_sizes, int n_in,
                              void* d_out, int out_size) {
    (void)in_sizes; (void)n_in; (void)out_size;
    const int*   input  = (const int*)  d_in[0];
    const float* hidden = (const float*)d_in[2];
    const float* emb    = (const float*)d_in[3];
    const float* W_ih   = (const float*)d_in[4];
    const float* W_hh   = (const float*)d_in[5];
    const float* b_ih   = (const float*)d_in[6];
    const float* b_hh   = (const float*)d_in[7];
    float* out = (float*)d_out;

    const int RSMEM = 139264 + 2048;
    cudaFuncSetAttribute(k_recurrent, cudaFuncAttributeMaxDynamicSharedMemorySize, RSMEM);

    k_convert_wih<<<3072, 256>>>(W_ih);
    k_gather<<<8192, 256>>>(input, emb);
    k_init_h<<<256, 256>>>(hidden);

    dim3 ggrid(24, 256);
    k_gi_gemm<<<ggrid, 128>>>(b_ih);

    k_recurrent<<<RGRID, RTHR, RSMEM>>>(hidden, W_hh, b_hh, out);
}